// round 5
// baseline (speedup 1.0000x reference)
#include <cuda_runtime.h>

// ---------------------------------------------------------------------------
// DeepGCN fused kernel.
// Structure: graphs are fully independent (edges are intra-graph), so the
// whole 20-layer res+ GCN scan is fused into one persistent pass with the
// per-graph state held in registers/shared memory.
//
// Scatter-add is replaced by a constant 23x23 edge-multiplicity matrix A per
// graph (agg = A @ z), built once per launch from edge_index with atomics.
// ---------------------------------------------------------------------------

static constexpr int NUM_GRAPHS = 16384;
static constexpr int NG        = 23;       // nodes per graph
static constexpr int E_TOTAL   = 4194304;  // total edges
static constexpr int HDIM      = 64;
static constexpr int NLAYERS   = 20;
static constexpr int NB        = 1024;     // clips
static constexpr int NT        = 16;       // window
static constexpr int NC        = 3;        // classes
static constexpr int A_STRIDE  = NG * NG;  // 529

static constexpr int WPB     = 8;    // warps (=graphs) per block
static constexpr int ZSTRIDE = 24;   // z column stride (23 nodes + 1 zero pad)

// Shared layout (floats):
//  [0, 4096)      W_rel  (layer)
//  [4096, 8192)   W_root (layer)
//  [8192, 8256)   ln_g
//  [8256, 8320)   ln_b
//  [8320, 8384)   b_rel
//  [8384, 8896)   W_enc
//  [8896, 8960)   b_enc
//  [8960, +8*1536) per-warp z buffers (transposed: z[f*24 + node])
static constexpr int SM_FLOATS = 8960 + WPB * (HDIM * ZSTRIDE);
static constexpr int SM_BYTES  = SM_FLOATS * 4;  // 84992

// Device scratch (allocation-free rule: __device__ globals)
__device__ float g_A[(size_t)NUM_GRAPHS * A_STRIDE];   // ~34.7 MB
__device__ float g_pooled[(size_t)NUM_GRAPHS * HDIM];  // 4 MB

// ---------------------------------------------------------------------------
__global__ void zeroA_kernel() {
    const int n4 = NUM_GRAPHS * A_STRIDE / 4;
    float4* p = reinterpret_cast<float4*>(g_A);
    for (int i = blockIdx.x * blockDim.x + threadIdx.x; i < n4;
         i += gridDim.x * blockDim.x)
        p[i] = make_float4(0.f, 0.f, 0.f, 0.f);
}

__global__ void buildA_kernel(const int* __restrict__ ei) {
    int e = blockIdx.x * blockDim.x + threadIdx.x;
    if (e >= E_TOTAL) return;
    int s = ei[e];            // global src id
    int d = ei[E_TOTAL + e];  // global dst id
    int g  = d / NG;
    int li = d - g * NG;      // local dst
    int lj = s - g * NG;      // local src (same graph by construction)
    atomicAdd(&g_A[(size_t)g * A_STRIDE + li * NG + lj], 1.0f);
}

// ---------------------------------------------------------------------------
// Main fused kernel: encoder + 20 layers + per-graph mean pool.
// One warp per graph; lanes 0..22 own node rows (h[64] in registers).
// ---------------------------------------------------------------------------
__global__ void __launch_bounds__(32 * WPB, 2) gcn_main(
    const float* __restrict__ x,
    const float* __restrict__ W_enc, const float* __restrict__ b_enc,
    const float* __restrict__ ln_g,  const float* __restrict__ ln_b,
    const float* __restrict__ W_rel, const float* __restrict__ b_rel,
    const float* __restrict__ W_root)
{
    extern __shared__ float sm[];
    float* wrel_s  = sm;
    float* wroot_s = sm + 4096;
    float* lng_s   = sm + 8192;
    float* lnb_s   = sm + 8256;
    float* brel_s  = sm + 8320;
    float* wenc_s  = sm + 8384;
    float* benc_s  = sm + 8896;
    float* zall    = sm + 8960;

    const int tid  = threadIdx.x;
    const int warp = tid >> 5;
    const int lane = tid & 31;
    const int g    = blockIdx.x * WPB + warp;
    float* z_s = zall + warp * (HDIM * ZSTRIDE);

    // one-time loads: encoder weights; zero the (warp-private) z buffer so the
    // pad entries (row 23 of each column) are exactly 0 forever.
    for (int i = tid; i < 512; i += 32 * WPB) wenc_s[i] = W_enc[i];
    if (tid < HDIM) benc_s[tid] = b_enc[tid];
    for (int i = lane; i < HDIM * ZSTRIDE; i += 32) z_s[i] = 0.f;
    __syncthreads();

    const bool act = (lane < NG);

    float h[HDIM];
    float Arow[NG + 1];

    if (act) {
        // encoder: h = x @ W_enc + b_enc   (x row: 8 floats, 32B aligned)
        const float4* xr = reinterpret_cast<const float4*>(
            x + (size_t)(g * NG + lane) * 8);
        float4 xa = xr[0], xb = xr[1];
        float xv[8] = {xa.x, xa.y, xa.z, xa.w, xb.x, xb.y, xb.z, xb.w};
        #pragma unroll
        for (int f = 0; f < HDIM; f++) {
            float a = benc_s[f];
            #pragma unroll
            for (int k = 0; k < 8; k++) a = fmaf(xv[k], wenc_s[k * HDIM + f], a);
            h[f] = a;
        }
        // A row for this node (constant across layers)
        const float* Ar = g_A + (size_t)g * A_STRIDE + lane * NG;
        #pragma unroll
        for (int j = 0; j < NG; j++) Arow[j] = Ar[j];
    } else {
        #pragma unroll
        for (int f = 0; f < HDIM; f++) h[f] = 0.f;
        #pragma unroll
        for (int j = 0; j < NG; j++) Arow[j] = 0.f;
    }
    Arow[NG] = 0.f;  // pad (pairs with the zeroed z pad entry)

    for (int l = 0; l < NLAYERS; l++) {
        __syncthreads();  // all warps done reading previous layer's weights
        // stage this layer's weights
        {
            const float4* Wr4 = reinterpret_cast<const float4*>(W_rel)  + l * 1024;
            const float4* Wo4 = reinterpret_cast<const float4*>(W_root) + l * 1024;
            float4* dr = reinterpret_cast<float4*>(wrel_s);
            float4* dq = reinterpret_cast<float4*>(wroot_s);
            for (int i = tid; i < 1024; i += 32 * WPB) { dr[i] = Wr4[i]; dq[i] = Wo4[i]; }
            if (tid < HDIM) {
                lng_s[tid]  = ln_g[l * HDIM + tid];
                lnb_s[tid]  = ln_b[l * HDIM + tid];
                brel_s[tid] = b_rel[l * HDIM + tid];
            }
        }
        __syncthreads();

        // z = relu(LayerNorm(h)) -> shared (transposed: z[f*24 + node])
        if (act) {
            float mu = 0.f;
            #pragma unroll
            for (int f = 0; f < HDIM; f++) mu += h[f];
            mu *= (1.f / HDIM);
            float var = 0.f;
            #pragma unroll
            for (int f = 0; f < HDIM; f++) { float d = h[f] - mu; var = fmaf(d, d, var); }
            var *= (1.f / HDIM);
            float rs = rsqrtf(var + 1e-5f);
            #pragma unroll
            for (int f = 0; f < HDIM; f++) {
                float zf = fmaf((h[f] - mu) * rs, lng_s[f], lnb_s[f]);
                z_s[f * ZSTRIDE + lane] = fmaxf(zf, 0.f);
            }
        }
        __syncwarp();

        // h += b_rel + (A@z) @ W_rel + z @ W_root
        if (act) {
            #pragma unroll
            for (int f = 0; f < HDIM; f++) h[f] += brel_s[f];

            #pragma unroll 2
            for (int k = 0; k < HDIM; k++) {
                const float* zc = z_s + k * ZSTRIDE;       // column k (24 floats)
                const float4* zc4 = reinterpret_cast<const float4*>(zc);
                float a0 = 0.f, a1 = 0.f, a2 = 0.f, a3 = 0.f;
                #pragma unroll
                for (int j = 0; j < 6; j++) {              // 24 entries (pad=0)
                    float4 zv = zc4[j];
                    a0 = fmaf(Arow[4 * j + 0], zv.x, a0);
                    a1 = fmaf(Arow[4 * j + 1], zv.y, a1);
                    a2 = fmaf(Arow[4 * j + 2], zv.z, a2);
                    a3 = fmaf(Arow[4 * j + 3], zv.w, a3);
                }
                float a  = (a0 + a1) + (a2 + a3);          // agg[node][k]
                float zk = zc[lane];                       // z[node][k]

                const float4* wr = reinterpret_cast<const float4*>(wrel_s  + k * HDIM);
                const float4* wo = reinterpret_cast<const float4*>(wroot_s + k * HDIM);
                #pragma unroll
                for (int f4 = 0; f4 < 16; f4++) {
                    float4 w1 = wr[f4];
                    float4 w2 = wo[f4];
                    h[4 * f4 + 0] = fmaf(a, w1.x, fmaf(zk, w2.x, h[4 * f4 + 0]));
                    h[4 * f4 + 1] = fmaf(a, w1.y, fmaf(zk, w2.y, h[4 * f4 + 1]));
                    h[4 * f4 + 2] = fmaf(a, w1.z, fmaf(zk, w2.z, h[4 * f4 + 2]));
                    h[4 * f4 + 3] = fmaf(a, w1.w, fmaf(zk, w2.w, h[4 * f4 + 3]));
                }
            }
        }
    }

    // per-graph mean pool
    __syncwarp();
    if (act) {
        #pragma unroll
        for (int f = 0; f < HDIM; f++) z_s[f * ZSTRIDE + lane] = h[f];
    }
    __syncwarp();
    for (int f = lane; f < HDIM; f += 32) {
        float s = 0.f;
        #pragma unroll
        for (int i = 0; i < NG; i++) s += z_s[f * ZSTRIDE + i];
        g_pooled[(size_t)g * HDIM + f] = s * (1.f / NG);
    }
}

// ---------------------------------------------------------------------------
// Head: xt = pooled.reshape(B,T,H)+pos; v = mean_t; out = relu(v@W1+b1)@W2+b2
// ---------------------------------------------------------------------------
__global__ void head_kernel(const float* __restrict__ pos,
                            const float* __restrict__ W1, const float* __restrict__ b1,
                            const float* __restrict__ W2, const float* __restrict__ b2,
                            float* __restrict__ out)
{
    __shared__ float vs[HDIM];
    __shared__ float h1s[HDIM];
    const int b = blockIdx.x;
    const int f = threadIdx.x;

    float v = 0.f;
    #pragma unroll
    for (int t = 0; t < NT; t++)
        v += g_pooled[(size_t)(b * NT + t) * HDIM + f] + pos[t * HDIM + f];
    vs[f] = v * (1.f / NT);
    __syncthreads();

    float acc = b1[f];
    #pragma unroll
    for (int k = 0; k < HDIM; k++) acc = fmaf(vs[k], W1[k * HDIM + f], acc);
    h1s[f] = fmaxf(acc, 0.f);
    __syncthreads();

    if (f < NC) {
        float o = b2[f];
        #pragma unroll
        for (int k = 0; k < HDIM; k++) o = fmaf(h1s[k], W2[k * NC + f], o);
        out[b * NC + f] = o;
    }
}

// ---------------------------------------------------------------------------
extern "C" void kernel_launch(void* const* d_in, const int* in_sizes, int n_in,
                              void* d_out, int out_size)
{
    const float* x     = (const float*)d_in[0];
    const int*   ei    = (const int*)  d_in[1];
    // d_in[2] = batch (unused: graphs are contiguous blocks of 23 nodes)
    const float* W_enc = (const float*)d_in[3];
    const float* b_enc = (const float*)d_in[4];
    const float* ln_g  = (const float*)d_in[5];
    const float* ln_b  = (const float*)d_in[6];
    const float* W_rel = (const float*)d_in[7];
    const float* b_rel = (const float*)d_in[8];
    const float* W_root= (const float*)d_in[9];
    const float* pos   = (const float*)d_in[10];
    const float* W1    = (const float*)d_in[11];
    const float* b1    = (const float*)d_in[12];
    const float* W2    = (const float*)d_in[13];
    const float* b2    = (const float*)d_in[14];
    float* out = (float*)d_out;

    (void)in_sizes; (void)n_in; (void)out_size;

    // opt-in to >48KB dynamic shared (idempotent host call; not a stream op)
    cudaFuncSetAttribute(gcn_main, cudaFuncAttributeMaxDynamicSharedMemorySize,
                         SM_BYTES);

    zeroA_kernel<<<1024, 256>>>();
    buildA_kernel<<<(E_TOTAL + 255) / 256, 256>>>(ei);
    gcn_main<<<NUM_GRAPHS / WPB, 32 * WPB, SM_BYTES>>>(
        x, W_enc, b_enc, ln_g, ln_b, W_rel, b_rel, W_root);
    head_kernel<<<NB, HDIM>>>(pos, W1, b1, W2, b2, out);
}

// round 6
// speedup vs baseline: 1.5352x; 1.5352x over previous
#include <cuda_runtime.h>

// ---------------------------------------------------------------------------
// DeepGCN fused kernel, round 5.
//  - Graphs are independent -> entire 20-layer res+ scan fused, h in registers.
//  - Scatter-add replaced by per-graph 23x23 edge-multiplicity matrix A
//    (built once per launch), so every layer is dense math.
//  - NEW: packed fp32 math via PTX fma.rn.f32x2 (halves FMA instruction count;
//    ptxas never emits FFMA2 from C++), and TWO graphs per warp so each
//    broadcast weight LDS feeds 2x the FMAs (keeps the kernel FMA-bound).
// ---------------------------------------------------------------------------

static constexpr int NUM_GRAPHS = 16384;
static constexpr int NG        = 23;       // nodes per graph
static constexpr int E_TOTAL   = 4194304;  // total edges
static constexpr int HDIM      = 64;
static constexpr int NLAYERS   = 20;
static constexpr int NB        = 1024;     // clips
static constexpr int NT        = 16;       // window
static constexpr int NC        = 3;        // classes
static constexpr int A_STRIDE  = NG * NG;  // 529

static constexpr int WPB     = 4;    // warps per block (each warp = 2 graphs)
static constexpr int GPB     = WPB * 2;  // graphs per block
static constexpr int ZSTRIDE = 24;   // z column stride (23 nodes + 1 zero pad)
static constexpr int ZBUF    = HDIM * ZSTRIDE;  // 1536 floats per graph

// Shared layout (floats):
//  [0, 4096)      W_rel  (current layer)
//  [4096, 8192)   W_root (current layer)
//  [8192, 8256)   ln_g
//  [8256, 8320)   ln_b
//  [8320, 8384)   b_rel
//  [8384, 8896)   W_enc
//  [8896, 8960)   b_enc
//  [8960, +GPB*1536) per-graph z buffers (transposed: z[f*24 + node])
static constexpr int SM_FLOATS = 8960 + GPB * ZBUF;
static constexpr int SM_BYTES  = SM_FLOATS * 4;   // 84992 B/block, 2 blocks/SM

// Device scratch (allocation-free rule: __device__ globals)
__device__ float g_A[(size_t)NUM_GRAPHS * A_STRIDE];   // ~34.7 MB
__device__ float g_pooled[(size_t)NUM_GRAPHS * HDIM];  // 4 MB

// ---------------------------------------------------------------------------
// f32x2 packed helpers (only reachable via PTX on sm_103a)
// ---------------------------------------------------------------------------
typedef unsigned long long u64t;

__device__ __forceinline__ u64t pk2(float lo, float hi) {
    u64t r;
    asm("mov.b64 %0, {%1, %2};" : "=l"(r) : "f"(lo), "f"(hi));
    return r;
}
__device__ __forceinline__ void upk2(u64t v, float& lo, float& hi) {
    asm("mov.b64 {%0, %1}, %2;" : "=f"(lo), "=f"(hi) : "l"(v));
}
__device__ __forceinline__ u64t fma2(u64t a, u64t b, u64t c) {
    u64t d;
    asm("fma.rn.f32x2 %0, %1, %2, %3;" : "=l"(d) : "l"(a), "l"(b), "l"(c));
    return d;
}
__device__ __forceinline__ u64t add2(u64t a, u64t b) {
    u64t d;
    asm("add.rn.f32x2 %0, %1, %2;" : "=l"(d) : "l"(a), "l"(b));
    return d;
}
__device__ __forceinline__ u64t mul2(u64t a, u64t b) {
    u64t d;
    asm("mul.rn.f32x2 %0, %1, %2;" : "=l"(d) : "l"(a), "l"(b));
    return d;
}

// ---------------------------------------------------------------------------
__global__ void zeroA_kernel() {
    const int n4 = NUM_GRAPHS * A_STRIDE / 4;
    float4* p = reinterpret_cast<float4*>(g_A);
    for (int i = blockIdx.x * blockDim.x + threadIdx.x; i < n4;
         i += gridDim.x * blockDim.x)
        p[i] = make_float4(0.f, 0.f, 0.f, 0.f);
}

__global__ void buildA_kernel(const int* __restrict__ ei) {
    int e = blockIdx.x * blockDim.x + threadIdx.x;
    if (e >= E_TOTAL) return;
    int s = ei[e];            // global src id
    int d = ei[E_TOTAL + e];  // global dst id
    int g  = d / NG;
    int li = d - g * NG;      // local dst
    int lj = s - g * NG;      // local src (same graph by construction)
    atomicAdd(&g_A[(size_t)g * A_STRIDE + li * NG + lj], 1.0f);
}

// ---------------------------------------------------------------------------
// Main fused kernel: encoder + 20 layers + per-graph mean pool.
// One warp per TWO graphs; lanes 0..22 own one node row of each graph,
// h held as packed f32x2 registers (32 u64 per graph).
// ---------------------------------------------------------------------------
__global__ void __launch_bounds__(32 * WPB, 2) gcn_main(
    const float* __restrict__ x,
    const float* __restrict__ W_enc, const float* __restrict__ b_enc,
    const float* __restrict__ ln_g,  const float* __restrict__ ln_b,
    const float* __restrict__ W_rel, const float* __restrict__ b_rel,
    const float* __restrict__ W_root)
{
    extern __shared__ float sm[];
    float* wrel_s  = sm;
    float* wroot_s = sm + 4096;
    float* lng_s   = sm + 8192;
    float* lnb_s   = sm + 8256;
    float* brel_s  = sm + 8320;
    float* wenc_s  = sm + 8384;
    float* benc_s  = sm + 8896;
    float* zall    = sm + 8960;

    const int tid  = threadIdx.x;
    const int warp = tid >> 5;
    const int lane = tid & 31;
    const int gA   = blockIdx.x * GPB + warp * 2;
    const int gB   = gA + 1;
    float* zA = zall + (warp * 2 + 0) * ZBUF;
    float* zB = zall + (warp * 2 + 1) * ZBUF;

    // one-time: encoder weights to shared; zero z buffers (pad rows stay 0)
    for (int i = tid; i < 512; i += 32 * WPB) wenc_s[i] = W_enc[i];
    if (tid < HDIM) benc_s[tid] = b_enc[tid];
    for (int i = lane; i < ZBUF; i += 32) { zA[i] = 0.f; zB[i] = 0.f; }
    __syncthreads();

    const bool act = (lane < NG);

    u64t hA[HDIM / 2], hB[HDIM / 2];   // packed h (f32x2)
    u64t ApA[12], ApB[12];             // packed A rows (23 + zero pad)

    if (act) {
        // encoder for both graphs: h = x @ W_enc + b_enc
        const float4* xrA = reinterpret_cast<const float4*>(
            x + (size_t)(gA * NG + lane) * 8);
        const float4* xrB = reinterpret_cast<const float4*>(
            x + (size_t)(gB * NG + lane) * 8);
        float4 a0 = xrA[0], a1 = xrA[1], b0 = xrB[0], b1 = xrB[1];
        float xa[8] = {a0.x, a0.y, a0.z, a0.w, a1.x, a1.y, a1.z, a1.w};
        float xb[8] = {b0.x, b0.y, b0.z, b0.w, b1.x, b1.y, b1.z, b1.w};
        #pragma unroll
        for (int p = 0; p < HDIM / 2; p++) {
            float va0 = benc_s[2 * p], va1 = benc_s[2 * p + 1];
            float vb0 = va0, vb1 = va1;
            #pragma unroll
            for (int k = 0; k < 8; k++) {
                float w0 = wenc_s[k * HDIM + 2 * p];
                float w1 = wenc_s[k * HDIM + 2 * p + 1];
                va0 = fmaf(xa[k], w0, va0); va1 = fmaf(xa[k], w1, va1);
                vb0 = fmaf(xb[k], w0, vb0); vb1 = fmaf(xb[k], w1, vb1);
            }
            hA[p] = pk2(va0, va1);
            hB[p] = pk2(vb0, vb1);
        }
        // packed A rows (constant across layers)
        const float* ArA = g_A + (size_t)gA * A_STRIDE + lane * NG;
        const float* ArB = g_A + (size_t)gB * A_STRIDE + lane * NG;
        #pragma unroll
        for (int j = 0; j < 11; j++) {
            ApA[j] = pk2(ArA[2 * j], ArA[2 * j + 1]);
            ApB[j] = pk2(ArB[2 * j], ArB[2 * j + 1]);
        }
        ApA[11] = pk2(ArA[22], 0.f);   // pad pairs with zeroed z pad entry
        ApB[11] = pk2(ArB[22], 0.f);
    } else {
        #pragma unroll
        for (int p = 0; p < HDIM / 2; p++) { hA[p] = 0ull; hB[p] = 0ull; }
        #pragma unroll
        for (int j = 0; j < 12; j++) { ApA[j] = 0ull; ApB[j] = 0ull; }
    }

    const u64t neg1 = pk2(-1.f, -1.f);

    for (int l = 0; l < NLAYERS; l++) {
        __syncthreads();  // previous layer's weight reads complete
        // stage this layer's weights
        {
            const float4* Wr4 = reinterpret_cast<const float4*>(W_rel)  + l * 1024;
            const float4* Wo4 = reinterpret_cast<const float4*>(W_root) + l * 1024;
            float4* dr = reinterpret_cast<float4*>(wrel_s);
            float4* dq = reinterpret_cast<float4*>(wroot_s);
            for (int i = tid; i < 1024; i += 32 * WPB) { dr[i] = Wr4[i]; dq[i] = Wo4[i]; }
            if (tid < HDIM) {
                lng_s[tid]  = ln_g[l * HDIM + tid];
                lnb_s[tid]  = ln_b[l * HDIM + tid];
                brel_s[tid] = b_rel[l * HDIM + tid];
            }
        }
        __syncthreads();

        // z = relu(LayerNorm(h)) -> shared (transposed: z[f*24 + node])
        if (act) {
            const u64t* g8 = reinterpret_cast<const u64t*>(lng_s);
            const u64t* q8 = reinterpret_cast<const u64t*>(lnb_s);

            #pragma unroll
            for (int gg = 0; gg < 2; gg++) {
                u64t* h2  = gg ? hB : hA;
                float* zs = gg ? zB : zA;
                // mean
                u64t s2 = h2[0];
                #pragma unroll
                for (int p = 1; p < 32; p++) s2 = add2(s2, h2[p]);
                float slo, shi; upk2(s2, slo, shi);
                float mu = (slo + shi) * (1.f / HDIM);
                u64t mu2 = pk2(mu, mu);
                // var
                u64t v2 = 0ull;
                #pragma unroll
                for (int p = 0; p < 32; p++) {
                    u64t d = fma2(mu2, neg1, h2[p]);
                    v2 = fma2(d, d, v2);
                }
                float vlo, vhi; upk2(v2, vlo, vhi);
                float rs = rsqrtf((vlo + vhi) * (1.f / HDIM) + 1e-5f);
                u64t rs2 = pk2(rs, rs);
                // z
                #pragma unroll
                for (int p = 0; p < 32; p++) {
                    u64t d  = fma2(mu2, neg1, h2[p]);
                    u64t m  = mul2(d, rs2);
                    u64t zz = fma2(m, g8[p], q8[p]);
                    float zlo, zhi; upk2(zz, zlo, zhi);
                    zs[(2 * p)     * ZSTRIDE + lane] = fmaxf(zlo, 0.f);
                    zs[(2 * p + 1) * ZSTRIDE + lane] = fmaxf(zhi, 0.f);
                }
            }
        }
        __syncwarp();

        // h += b_rel + (A@z) @ W_rel + z @ W_root     (packed f32x2)
        if (act) {
            const u64t* br8 = reinterpret_cast<const u64t*>(brel_s);
            #pragma unroll
            for (int p = 0; p < 32; p++) {
                hA[p] = add2(hA[p], br8[p]);
                hB[p] = add2(hB[p], br8[p]);
            }

            #pragma unroll 2
            for (int k = 0; k < HDIM; k++) {
                const float* zcA = zA + k * ZSTRIDE;
                const float* zcB = zB + k * ZSTRIDE;
                const ulonglong2* zA2 = reinterpret_cast<const ulonglong2*>(zcA);
                const ulonglong2* zB2 = reinterpret_cast<const ulonglong2*>(zcB);

                // agg[node][k] = Arow . z(:,k)   (12 packed FMAs each)
                u64t accA = 0ull, accB = 0ull;
                #pragma unroll
                for (int j = 0; j < 6; j++) {
                    ulonglong2 za = zA2[j];
                    ulonglong2 zb = zB2[j];
                    accA = fma2(ApA[2 * j],     za.x, accA);
                    accA = fma2(ApA[2 * j + 1], za.y, accA);
                    accB = fma2(ApB[2 * j],     zb.x, accB);
                    accB = fma2(ApB[2 * j + 1], zb.y, accB);
                }
                float alo, ahi; upk2(accA, alo, ahi);
                float aAv = alo + ahi;
                upk2(accB, alo, ahi);
                float aBv = alo + ahi;

                u64t a2A  = pk2(aAv, aAv);
                u64t a2B  = pk2(aBv, aBv);
                u64t zk2A = pk2(zcA[lane], zcA[lane]);
                u64t zk2B = pk2(zcB[lane], zcB[lane]);

                const ulonglong2* wr2 =
                    reinterpret_cast<const ulonglong2*>(wrel_s + k * HDIM);
                const ulonglong2* wo2 =
                    reinterpret_cast<const ulonglong2*>(wroot_s + k * HDIM);
                #pragma unroll
                for (int q = 0; q < 16; q++) {
                    ulonglong2 w1 = wr2[q];
                    ulonglong2 w2 = wo2[q];
                    hA[2 * q]     = fma2(a2A, w1.x, fma2(zk2A, w2.x, hA[2 * q]));
                    hA[2 * q + 1] = fma2(a2A, w1.y, fma2(zk2A, w2.y, hA[2 * q + 1]));
                    hB[2 * q]     = fma2(a2B, w1.x, fma2(zk2B, w2.x, hB[2 * q]));
                    hB[2 * q + 1] = fma2(a2B, w1.y, fma2(zk2B, w2.y, hB[2 * q + 1]));
                }
            }
        }
    }

    // per-graph mean pool (reuse z buffers)
    __syncwarp();
    if (act) {
        #pragma unroll
        for (int p = 0; p < 32; p++) {
            float lo, hi;
            upk2(hA[p], lo, hi);
            zA[(2 * p) * ZSTRIDE + lane] = lo;
            zA[(2 * p + 1) * ZSTRIDE + lane] = hi;
            upk2(hB[p], lo, hi);
            zB[(2 * p) * ZSTRIDE + lane] = lo;
            zB[(2 * p + 1) * ZSTRIDE + lane] = hi;
        }
    }
    __syncwarp();
    for (int f = lane; f < HDIM; f += 32) {
        float sA = 0.f, sB = 0.f;
        #pragma unroll
        for (int i = 0; i < NG; i++) {
            sA += zA[f * ZSTRIDE + i];
            sB += zB[f * ZSTRIDE + i];
        }
        g_pooled[(size_t)gA * HDIM + f] = sA * (1.f / NG);
        g_pooled[(size_t)gB * HDIM + f] = sB * (1.f / NG);
    }
}

// ---------------------------------------------------------------------------
// Head: xt = pooled.reshape(B,T,H)+pos; v = mean_t; out = relu(v@W1+b1)@W2+b2
// ---------------------------------------------------------------------------
__global__ void head_kernel(const float* __restrict__ pos,
                            const float* __restrict__ W1, const float* __restrict__ b1,
                            const float* __restrict__ W2, const float* __restrict__ b2,
                            float* __restrict__ out)
{
    __shared__ float vs[HDIM];
    __shared__ float h1s[HDIM];
    const int b = blockIdx.x;
    const int f = threadIdx.x;

    float v = 0.f;
    #pragma unroll
    for (int t = 0; t < NT; t++)
        v += g_pooled[(size_t)(b * NT + t) * HDIM + f] + pos[t * HDIM + f];
    vs[f] = v * (1.f / NT);
    __syncthreads();

    float acc = b1[f];
    #pragma unroll
    for (int k = 0; k < HDIM; k++) acc = fmaf(vs[k], W1[k * HDIM + f], acc);
    h1s[f] = fmaxf(acc, 0.f);
    __syncthreads();

    if (f < NC) {
        float o = b2[f];
        #pragma unroll
        for (int k = 0; k < HDIM; k++) o = fmaf(h1s[k], W2[k * NC + f], o);
        out[b * NC + f] = o;
    }
}

// ---------------------------------------------------------------------------
extern "C" void kernel_launch(void* const* d_in, const int* in_sizes, int n_in,
                              void* d_out, int out_size)
{
    const float* x     = (const float*)d_in[0];
    const int*   ei    = (const int*)  d_in[1];
    // d_in[2] = batch (unused: graphs are contiguous blocks of 23 nodes)
    const float* W_enc = (const float*)d_in[3];
    const float* b_enc = (const float*)d_in[4];
    const float* ln_g  = (const float*)d_in[5];
    const float* ln_b  = (const float*)d_in[6];
    const float* W_rel = (const float*)d_in[7];
    const float* b_rel = (const float*)d_in[8];
    const float* W_root= (const float*)d_in[9];
    const float* pos   = (const float*)d_in[10];
    const float* W1    = (const float*)d_in[11];
    const float* b1    = (const float*)d_in[12];
    const float* W2    = (const float*)d_in[13];
    const float* b2    = (const float*)d_in[14];
    float* out = (float*)d_out;

    (void)in_sizes; (void)n_in; (void)out_size;

    cudaFuncSetAttribute(gcn_main, cudaFuncAttributeMaxDynamicSharedMemorySize,
                         SM_BYTES);

    zeroA_kernel<<<1024, 256>>>();
    buildA_kernel<<<(E_TOTAL + 255) / 256, 256>>>(ei);
    gcn_main<<<NUM_GRAPHS / GPB, 32 * WPB, SM_BYTES>>>(
        x, W_enc, b_enc, ln_g, ln_b, W_rel, b_rel, W_root);
    head_kernel<<<NB, HDIM>>>(pos, W1, b1, W2, b2, out);
}